// round 4
// baseline (speedup 1.0000x reference)
#include <cuda_runtime.h>

#define HH    512
#define WW    512
#define HW    (HH * WW)
#define PAD   8
#define NKH   32
#define NKW   32
#define NK    1024
#define NC    33            // stride cells per dim (528/16)
#define BATCH 64

// Init: out[b,n] = bias[n]. Full overwrite -> graph-replay idempotent.
__global__ __launch_bounds__(256) void bslc_init(
    const float* __restrict__ bias, float* __restrict__ out)
{
    const int idx = blockIdx.x * 256 + threadIdx.x;   // b*NK + n
    out[idx] = bias[idx & (NK - 1)];
}

// Main: one block per 16x16 stride cell of the padded image.
// Cell (Ri,Ci) covers padded pixels [16Ri,16Ri+16) x [16Ci,16Ci+16); those
// pixels feed windows (Ri-i, Ci-j), i,j in {0,1}, at kernel offsets
// (dy+16i, dx+16j)  -> 4 "quadrants" q = i*2+j.
//
// Layout: 8 warps; warp w owns pixel-quads 8w..8w+7 (float4 granularity).
// lane = batch (handles batches lane and lane+32). Weights are warp-uniform
// (one broadcast LDG.128 per quadrant per quad). Each lane accumulates its
// own batches -> no cross-lane reduction; warps combine through 8KB smem,
// then one atomicAdd per (batch, quadrant) into bias-initialized out.
__global__ __launch_bounds__(256) void bslc_main(
    const float* __restrict__ x,       // (64,1,512,512)
    const float* __restrict__ weight,  // (NK,1024)
    float* __restrict__ out)           // (64,NK) = bias-initialized
{
    const int cell = blockIdx.x;
    const int Ri = cell / NC, Ci = cell % NC;
    const int tid  = threadIdx.x;
    const int lane = tid & 31;
    const int warp = tid >> 5;

    __shared__ float sred[8][2][4][32];   // [warp][batch-half][quadrant][lane]

    // Quadrant windows + validity (uniform across block).
    // NOTE: full 4-sided check — Ri,Ci reach 32, so r,c can equal NKH/NKW.
    int nq[4]; bool vq[4];
#pragma unroll
    for (int q = 0; q < 4; q++) {
        const int r = Ri - (q >> 1), c = Ci - (q & 1);
        vq[q] = (r >= 0) && (r < NKH) && (c >= 0) && (c < NKW);
        nq[q] = vq[q] ? (r * NKW + c) : 0;
    }

    float a[2][4] = {{0.f,0.f,0.f,0.f},{0.f,0.f,0.f,0.f}};

    const float* __restrict__ xb = x + (size_t)lane * HW;

#pragma unroll
    for (int k = 0; k < 8; k++) {
        const int qd  = warp * 8 + k;        // float4-quad index in cell
        const int dy  = qd >> 2;
        const int dx4 = (qd & 3) << 2;

        // Warp-uniform weight float4 per quadrant
        float4 wq[4];
#pragma unroll
        for (int q = 0; q < 4; q++) {
            float4 w = make_float4(0.f, 0.f, 0.f, 0.f);
            if (vq[q])
                w = *reinterpret_cast<const float4*>(
                        weight + nq[q] * 1024
                               + (dy  + 16 * (q >> 1)) * 32
                               + (dx4 + 16 * (q & 1)));
            wq[q] = w;
        }

        // Per-lane x gather (uniform predicate; 16B aligned)
        const int uy = Ri * 16 + dy  - PAD;
        const int ux = Ci * 16 + dx4 - PAD;
        const bool ok = ((unsigned)uy < (unsigned)HH) &&
                        ((unsigned)ux <= (unsigned)(WW - 4));
        float4 x0 = make_float4(0.f, 0.f, 0.f, 0.f);
        float4 x1 = x0;
        if (ok) {
            const float* p = xb + uy * WW + ux;
            x0 = *reinterpret_cast<const float4*>(p);
            x1 = *reinterpret_cast<const float4*>(p + 32 * HW);
        }

#pragma unroll
        for (int q = 0; q < 4; q++) {
            a[0][q] = fmaf(x0.x, wq[q].x, a[0][q]);
            a[0][q] = fmaf(x0.y, wq[q].y, a[0][q]);
            a[0][q] = fmaf(x0.z, wq[q].z, a[0][q]);
            a[0][q] = fmaf(x0.w, wq[q].w, a[0][q]);
            a[1][q] = fmaf(x1.x, wq[q].x, a[1][q]);
            a[1][q] = fmaf(x1.y, wq[q].y, a[1][q]);
            a[1][q] = fmaf(x1.z, wq[q].z, a[1][q]);
            a[1][q] = fmaf(x1.w, wq[q].w, a[1][q]);
        }
    }

#pragma unroll
    for (int t = 0; t < 2; t++)
#pragma unroll
        for (int q = 0; q < 4; q++)
            sred[warp][t][q][lane] = a[t][q];
    __syncthreads();

    // 256 threads = (quadrant q = warp>>1, batch b = tid&63) pairs.
    // Sum the 8 warps' partials; fixed order -> deterministic per block.
    {
        const int q = warp >> 1;           // uniform per warp
        const int b = tid & 63;
        const int t = b >> 5, l = b & 31;
        float s = 0.f;
#pragma unroll
        for (int w = 0; w < 8; w++)
            s += sred[w][t][q][l];

        const int r = Ri - (q >> 1), c = Ci - (q & 1);
        if (r >= 0 && r < NKH && c >= 0 && c < NKW)
            atomicAdd(out + (size_t)b * NK + r * NKW + c, s);
    }
}

extern "C" void kernel_launch(void* const* d_in, const int* in_sizes, int n_in,
                              void* d_out, int out_size)
{
    const float* x      = (const float*)d_in[0];   // (64,1,512,512) fp32
    const float* weight = (const float*)d_in[1];   // (1024,1024)    fp32
    const float* bias   = (const float*)d_in[2];   // (1024,)        fp32
    float*       out    = (float*)d_out;           // (64,32,32)     fp32

    bslc_init<<<(BATCH * NK) / 256, 256>>>(bias, out);
    bslc_main<<<NC * NC, 256>>>(x, weight, out);
}

// round 5
// speedup vs baseline: 1.3816x; 1.3816x over previous
#include <cuda_runtime.h>

#define HH    512
#define WW    512
#define HW    (HH * WW)
#define PAD   8
#define NKH   32
#define NKW   32
#define NK    1024
#define NC    33            // stride cells per dim (528/16)
#define BATCH 64

// Init: out[b,n] = bias[n]. Full overwrite -> graph-replay idempotent.
__global__ __launch_bounds__(256) void bslc_init(
    const float* __restrict__ bias, float* __restrict__ out)
{
    const int idx = blockIdx.x * 256 + threadIdx.x;   // b*NK + n
    out[idx] = bias[idx & (NK - 1)];
}

// One block per 16x16 stride cell. Cell (Ri,Ci) covers padded pixels
// [16Ri,16Ri+16) x [16Ci,16Ci+16); those feed windows (Ri-i, Ci-j),
// i,j in {0,1}, at kernel offsets (dy+16i, dx+16j) -> quadrants q=i*2+j.
//
// Warp w owns batches 8w..8w+7. Lane l owns pixel-quads l and l+32 (float4
// granularity) -> the warp covers the whole 256-px cell, so x loads are
// coalesced (8 x 64B rows per LDG.128) and each pixel is read exactly once.
// Weights are lane-private registers loaded once per block (8 float4/lane).
// Per batch: 32 FMAs, a 4-value warp butterfly, 4 atomicAdds into
// bias-initialized out. No shared memory.
__global__ __launch_bounds__(256) void bslc_main(
    const float* __restrict__ x,       // (64,1,512,512)
    const float* __restrict__ weight,  // (NK,1024)
    float* __restrict__ out)           // (64,NK) = bias-initialized
{
    const int cell = blockIdx.x;
    const int Ri = cell / NC, Ci = cell % NC;
    const int lane = threadIdx.x & 31;
    const int warp = threadIdx.x >> 5;

    // Quadrant windows + validity (uniform across block, full 4-sided check)
    int nq[4]; bool vq[4];
#pragma unroll
    for (int q = 0; q < 4; q++) {
        const int r = Ri - (q >> 1), c = Ci - (q & 1);
        vq[q] = (r >= 0) && (r < NKH) && (c >= 0) && (c < NKW);
        nq[q] = vq[q] ? (r * NKW + c) : 0;
    }
    // Pre-resolve lane->quadrant select for the final atomic (lanes 0..3)
    const int  nsel = (lane == 0) ? nq[0] : (lane == 1) ? nq[1]
                    : (lane == 2) ? nq[2] : nq[3];
    const bool vsel = (lane == 0) ? vq[0] : (lane == 1) ? vq[1]
                    : (lane == 2) ? vq[2] : vq[3];

    // Lane's two pixel-quads: s=0 -> quad lane (rows 0..7),
    //                         s=1 -> quad lane+32 (rows 8..15)
    const int dx4 = (lane & 3) << 2;
    float4 wreg[2][4];
    bool   ok[2];
    int    off[2];
#pragma unroll
    for (int s = 0; s < 2; s++) {
        const int dy = (lane >> 2) + 8 * s;
#pragma unroll
        for (int q = 0; q < 4; q++) {
            float4 w = make_float4(0.f, 0.f, 0.f, 0.f);
            if (vq[q])
                w = *reinterpret_cast<const float4*>(
                        weight + nq[q] * 1024
                               + (dy  + 16 * (q >> 1)) * 32
                               + (dx4 + 16 * (q & 1)));
            wreg[s][q] = w;
        }
        const int uy = Ri * 16 + dy  - PAD;
        const int ux = Ci * 16 + dx4 - PAD;
        ok[s]  = ((unsigned)uy < (unsigned)HH) &&
                 ((unsigned)ux <= (unsigned)(WW - 4));
        off[s] = uy * WW + ux;
    }

    const int b0 = warp * 8;

#pragma unroll
    for (int t = 0; t < 8; t++) {
        const float* __restrict__ xb = x + (size_t)(b0 + t) * HW;
        float4 x0 = make_float4(0.f, 0.f, 0.f, 0.f);
        float4 x1 = x0;
        if (ok[0]) x0 = *reinterpret_cast<const float4*>(xb + off[0]);
        if (ok[1]) x1 = *reinterpret_cast<const float4*>(xb + off[1]);

        float a[4];
#pragma unroll
        for (int q = 0; q < 4; q++) {
            float s = 0.f;
            s = fmaf(x0.x, wreg[0][q].x, s);
            s = fmaf(x0.y, wreg[0][q].y, s);
            s = fmaf(x0.z, wreg[0][q].z, s);
            s = fmaf(x0.w, wreg[0][q].w, s);
            s = fmaf(x1.x, wreg[1][q].x, s);
            s = fmaf(x1.y, wreg[1][q].y, s);
            s = fmaf(x1.z, wreg[1][q].z, s);
            s = fmaf(x1.w, wreg[1][q].w, s);
            a[q] = s;
        }

        // Butterfly over the 32 lanes (256 cell pixels)
#pragma unroll
        for (int o = 16; o; o >>= 1) {
            a[0] += __shfl_xor_sync(0xffffffffu, a[0], o);
            a[1] += __shfl_xor_sync(0xffffffffu, a[1], o);
            a[2] += __shfl_xor_sync(0xffffffffu, a[2], o);
            a[3] += __shfl_xor_sync(0xffffffffu, a[3], o);
        }

        if (lane < 4 && vsel) {
            const float v = (lane == 0) ? a[0] : (lane == 1) ? a[1]
                          : (lane == 2) ? a[2] : a[3];
            atomicAdd(out + (size_t)(b0 + t) * NK + nsel, v);
        }
    }
}

extern "C" void kernel_launch(void* const* d_in, const int* in_sizes, int n_in,
                              void* d_out, int out_size)
{
    const float* x      = (const float*)d_in[0];   // (64,1,512,512) fp32
    const float* weight = (const float*)d_in[1];   // (1024,1024)    fp32
    const float* bias   = (const float*)d_in[2];   // (1024,)        fp32
    float*       out    = (float*)d_out;           // (64,32,32)     fp32

    bslc_init<<<(BATCH * NK) / 256, 256>>>(bias, out);
    bslc_main<<<NC * NC, 256>>>(x, weight, out);
}

// round 6
// speedup vs baseline: 1.8482x; 1.3378x over previous
#include <cuda_runtime.h>

#define HH    512
#define WW    512
#define HW    (HH * WW)
#define PAD   8
#define NKH   32
#define NKW   32
#define NK    1024
#define NC    33            // stride cells per dim (528/16)
#define BATCH 64
#define RPAD  36            // padded smem row (words): conflict-free LDS.128

// Init: out[b,n] = bias[n]. Full overwrite -> graph-replay idempotent.
__global__ __launch_bounds__(256) void bslc_init(
    const float* __restrict__ bias, float* __restrict__ out)
{
    const int idx = blockIdx.x * 256 + threadIdx.x;   // b*NK + n
    out[idx] = bias[idx & (NK - 1)];
}

// One block per 16x16 stride cell. Cell (Ri,Ci) covers padded pixels
// [16Ri,16Ri+16) x [16Ci,16Ci+16); those feed windows (Ri-i, Ci-j),
// i,j in {0,1}, at kernel offsets (dy+16i, dx+16j) -> quadrants q=i*2+j.
//
// Phase 1: warp w owns batches 8w..8w+7; lane l owns pixel-quads l and l+32
// (coalesced LDG.128, every x pixel read exactly once). Weights are
// lane-private registers loaded once per block. Per batch: 32 FMAs + 4 STS
// of quadrant partials. NO shuffles.
// Phase 2: after one __syncthreads, thread (b = tid>>2, q = tid&3) sums its
// 32-lane row from padded smem (8 conflict-free LDS.128) and does one
// atomicAdd into bias-initialized out.
__global__ __launch_bounds__(256) void bslc_main(
    const float* __restrict__ x,       // (64,1,512,512)
    const float* __restrict__ weight,  // (NK,1024)
    float* __restrict__ out)           // (64,NK) = bias-initialized
{
    // [warp][batch-in-warp][quadrant][lane + pad]
    __shared__ __align__(16) float sred[8][8][4][RPAD];

    const int cell = blockIdx.x;
    const int Ri = cell / NC, Ci = cell % NC;
    const int tid  = threadIdx.x;
    const int lane = tid & 31;
    const int warp = tid >> 5;

    // Quadrant windows + validity (uniform across block, full 4-sided check)
    int nq[4]; bool vq[4];
#pragma unroll
    for (int q = 0; q < 4; q++) {
        const int r = Ri - (q >> 1), c = Ci - (q & 1);
        vq[q] = (r >= 0) && (r < NKH) && (c >= 0) && (c < NKW);
        nq[q] = vq[q] ? (r * NKW + c) : 0;
    }

    // Lane's two pixel-quads: s=0 -> rows 0..7, s=1 -> rows 8..15 of cell
    const int dx4 = (lane & 3) << 2;
    float4 wreg[2][4];
    bool   ok[2];
    int    off[2];
#pragma unroll
    for (int s = 0; s < 2; s++) {
        const int dy = (lane >> 2) + 8 * s;
#pragma unroll
        for (int q = 0; q < 4; q++) {
            float4 w = make_float4(0.f, 0.f, 0.f, 0.f);
            if (vq[q])
                w = *reinterpret_cast<const float4*>(
                        weight + nq[q] * 1024
                               + (dy  + 16 * (q >> 1)) * 32
                               + (dx4 + 16 * (q & 1)));
            wreg[s][q] = w;
        }
        const int uy = Ri * 16 + dy  - PAD;
        const int ux = Ci * 16 + dx4 - PAD;
        ok[s]  = ((unsigned)uy < (unsigned)HH) &&
                 ((unsigned)ux <= (unsigned)(WW - 4));
        off[s] = uy * WW + ux;
    }

    const int b0 = warp * 8;

#pragma unroll
    for (int t = 0; t < 8; t++) {
        const float* __restrict__ xb = x + (size_t)(b0 + t) * HW;
        float4 x0 = make_float4(0.f, 0.f, 0.f, 0.f);
        float4 x1 = x0;
        if (ok[0]) x0 = *reinterpret_cast<const float4*>(xb + off[0]);
        if (ok[1]) x1 = *reinterpret_cast<const float4*>(xb + off[1]);

#pragma unroll
        for (int q = 0; q < 4; q++) {
            float s = 0.f;
            s = fmaf(x0.x, wreg[0][q].x, s);
            s = fmaf(x0.y, wreg[0][q].y, s);
            s = fmaf(x0.z, wreg[0][q].z, s);
            s = fmaf(x0.w, wreg[0][q].w, s);
            s = fmaf(x1.x, wreg[1][q].x, s);
            s = fmaf(x1.y, wreg[1][q].y, s);
            s = fmaf(x1.z, wreg[1][q].z, s);
            s = fmaf(x1.w, wreg[1][q].w, s);
            sred[warp][t][q][lane] = s;    // conflict-free STS.32
        }
    }

    __syncthreads();

    // Phase 2: thread -> (batch b, quadrant q); sum 32 lane partials.
    {
        const int b = tid >> 2;            // 0..63
        const int q = tid & 3;
        const float4* row =
            reinterpret_cast<const float4*>(&sred[b >> 3][b & 7][q][0]);
        float4 s4 = make_float4(0.f, 0.f, 0.f, 0.f);
#pragma unroll
        for (int i = 0; i < 8; i++) {
            const float4 v = row[i];
            s4.x += v.x; s4.y += v.y; s4.z += v.z; s4.w += v.w;
        }
        const float s = (s4.x + s4.y) + (s4.z + s4.w);

        const int r = Ri - (q >> 1), c = Ci - (q & 1);
        if (r >= 0 && r < NKH && c >= 0 && c < NKW)
            atomicAdd(out + (size_t)b * NK + r * NKW + c, s);
    }
}

extern "C" void kernel_launch(void* const* d_in, const int* in_sizes, int n_in,
                              void* d_out, int out_size)
{
    const float* x      = (const float*)d_in[0];   // (64,1,512,512) fp32
    const float* weight = (const float*)d_in[1];   // (1024,1024)    fp32
    const float* bias   = (const float*)d_in[2];   // (1024,)        fp32
    float*       out    = (float*)d_out;           // (64,32,32)     fp32

    bslc_init<<<(BATCH * NK) / 256, 256>>>(bias, out);
    bslc_main<<<NC * NC, 256>>>(x, weight, out);
}